// round 16
// baseline (speedup 1.0000x reference)
#include <cuda_runtime.h>
#include <math.h>

#define AN 120000
#define BN 8
#define CN 80
#define MN 32
#define NVALID 24
#define BLK 256
#define GX ((AN + BLK - 1) / BLK)     // 469
#define NBLOCKS (GX * BN)             // 3752
#define LN2 0.69314718055994530942f

__device__ double g_cls[BN];
__device__ double g_reg[BN];
__device__ int    g_np[BN];
__device__ unsigned int g_done;

__device__ __forceinline__ float smooth_l1(float d) {
    float ad = fabsf(d);
    return (ad <= (1.0f / 9.0f)) ? 4.5f * ad * ad : (ad - 0.5f / 9.0f);
}

// one group's focal sum in log2 domain
__device__ __forceinline__ float term4s(float4 v) {
    float o0 = fmaxf(1.0f - v.x, 1e-4f);
    float o1 = fmaxf(1.0f - v.y, 1e-4f);
    float o2 = fmaxf(1.0f - v.z, 1e-4f);
    float o3 = fmaxf(1.0f - v.w, 1e-4f);
    float s = v.x * v.x * __log2f(o0);
    s = fmaf(v.y * v.y, __log2f(o1), s);
    s = fmaf(v.z * v.z, __log2f(o2), s);
    s = fmaf(v.w * v.w, __log2f(o3), s);
    return s;
}

__global__ __launch_bounds__(BLK, 8) void focal_main(
    const float* __restrict__ cls,
    const float* __restrict__ reg,
    const float* __restrict__ anc,
    const float* __restrict__ lab,
    float* __restrict__ out)
{
    __shared__ float4  s_xy[MN];     // x1,y1,x2,y2 per gt box
    __shared__ float   s_area[MN];   // box area
    __shared__ float   s_cls[MN];    // box class
    __shared__ unsigned s_msk;       // validity ballot
    __shared__ float   s_w[BLK];     // per-anchor weight: 0 (ignore) or -0.75*ln2
    __shared__ float   s_rc[BLK / 32];
    __shared__ float   s_rr[BLK / 32];
    __shared__ int     s_rn[BLK / 32];
    __shared__ bool    s_last;

    const int b   = blockIdx.y;
    const int a0  = blockIdx.x * BLK;
    const int tid = threadIdx.x;
    const int nA  = min(BLK, AN - a0);

    // ---- entry prefetch: bursts 0 and 1 (2 x 20KB); overlaps phase A ----
    const float* cp = cls + ((size_t)b * AN + (size_t)a0) * CN;
    if (tid < 160) {
        asm volatile("prefetch.global.L2 [%0];" :: "l"(cp + tid * 32));
        if (nA == BLK)
            asm volatile("prefetch.global.L2 [%0];" :: "l"(cp + 5120 + tid * 32));
    }

    if (tid < 32) {
        const float* L = lab + ((size_t)b * MN + tid) * 5;
        float x1 = L[0], y1 = L[1], x2 = L[2], y2 = L[3], cl = L[4];
        s_xy[tid]   = make_float4(x1, y1, x2, y2);
        s_area[tid] = __fmul_rn(x2 - x1, y2 - y1);
        s_cls[tid]  = cl;
        unsigned m = __ballot_sync(0xffffffffu, cl != -1.0f);
        if (tid == 0) s_msk = m;
    }
    __syncthreads();

    float l_cls = 0.0f;
    float l_reg = 0.0f;
    int   l_np  = 0;
    float w_log2 = 0.0f;

    // ---- phase A: per-anchor IoU argmax, regression loss, positive correction ----
    if (tid < nA) {
        const int a = a0 + tid;
        const float4 av = __ldg(((const float4*)anc) + a);
        const float ax1 = av.x, ay1 = av.y, ax2 = av.z, ay2 = av.w;
        const float aw = ax2 - ax1, ah = ay2 - ay1;
        const float area_a = __fmul_rn(aw, ah);

        // argmax via cross-multiply: iou monotone in inter/sab
        float b_inter = -1.0f, b_sab = 1.0f;
        int   b_m = 0;

        if (s_msk == 0x00FFFFFFu) {
            // fast path: boxes 0..23 valid, 24..31 invalid (dataset invariant)
            #pragma unroll
            for (int m = 0; m < NVALID; m++) {
                float4 bx = s_xy[m];
                float iw = fmaxf(fminf(ax2, bx.z) - fmaxf(ax1, bx.x), 0.0f);
                float ih = fmaxf(fminf(ay2, bx.w) - fmaxf(ay1, bx.y), 0.0f);
                float inter = iw * ih;
                float sab   = area_a + s_area[m];
                if (inter * b_sab > b_inter * sab) {
                    b_inter = inter; b_sab = sab; b_m = m;
                }
            }
        } else {
            // generic fallback (any validity pattern)
            #pragma unroll
            for (int m = 0; m < MN; m++) {
                if (s_cls[m] < 0.0f) continue;
                float4 bx = s_xy[m];
                float iw = fmaxf(fminf(ax2, bx.z) - fmaxf(ax1, bx.x), 0.0f);
                float ih = fmaxf(fminf(ay2, bx.w) - fmaxf(ay1, bx.y), 0.0f);
                float inter = iw * ih;
                float sab   = area_a + s_area[m];
                if (inter * b_sab > b_inter * sab) {
                    b_inter = inter; b_sab = sab; b_m = m;
                }
            }
        }

        // exact IEEE recompute of winner's IoU (matches reference op-for-op)
        float4 bx = s_xy[b_m];
        float ab  = s_area[b_m];
        float iw = fmaxf(__fadd_rn(fminf(ax2, bx.z), -fmaxf(ax1, bx.x)), 0.0f);
        float ih = fmaxf(__fadd_rn(fminf(ay2, bx.w), -fmaxf(ay1, bx.y)), 0.0f);
        float inter = __fmul_rn(iw, ih);
        float ua = fmaxf(__fadd_rn(__fadd_rn(area_a, ab), -inter), 1e-8f);
        float iou = __fdiv_rn(inter, ua);

        if (iou >= 0.5f) {                       // positive anchor
            int code = (int)s_cls[b_m];
            l_np = 1;
            w_log2 = -0.75f * LN2;
            float gw_raw = bx.z - bx.x;
            float gh_raw = bx.w - bx.y;
            float gcx = bx.x + 0.5f * gw_raw;
            float gcy = bx.y + 0.5f * gh_raw;
            float gw = fmaxf(gw_raw, 1.0f);
            float gh = fmaxf(gh_raw, 1.0f);
            float acx = ax1 + 0.5f * aw;
            float acy = ay1 + 0.5f * ah;
            float t0 = __fdiv_rn(__fdiv_rn(gcx - acx, aw), 0.1f);
            float t1 = __fdiv_rn(__fdiv_rn(gcy - acy, ah), 0.1f);
            float t2 = __fdiv_rn(__logf(__fdiv_rn(gw, aw)), 0.2f);
            float t3 = __fdiv_rn(__logf(__fdiv_rn(gh, ah)), 0.2f);
            float4 rv = __ldg(((const float4*)reg) + ((size_t)b * AN + a));
            l_reg = smooth_l1(t0 - rv.x) + smooth_l1(t1 - rv.y)
                  + smooth_l1(t2 - rv.z) + smooth_l1(t3 - rv.w);
            // target-class correction: cancel streamed non-target term, add positive term
            float p    = __ldg(cls + ((size_t)b * AN + a) * CN + code);
            float pc   = fminf(fmaxf(p, 1e-4f), 1.0f - 1e-4f);
            float ompc = 1.0f - pc;
            float omp  = fmaxf(1.0f - p, 1e-4f);
            l_cls = 0.25f * ompc * ompc * (-__logf(pc))
                  + 0.75f * LN2 * (p * p * __log2f(omp));
        } else if (iou < 0.4f) {
            w_log2 = -0.75f * LN2;               // negative anchor
        }                                        // else ignore: w stays 0
    }
    s_w[tid] = w_log2;
    __syncthreads();   // load-bearing: synchronizes warps' LDG wavefronts

    // ---- phase B: block-strided weighted stream, MLP=5, rolling prefetch ----
    float acc0 = 0.0f, acc1 = 0.0f;
    const int STRIDE = BLK * 4;           // 1024 floats

    if (nA == BLK) {
        int e = tid * 4;
        #pragma unroll 1
        for (int i = 0; i < 4; i++) {
            float4 v0 = __ldcs((const float4*)(cp + e));
            float4 v1 = __ldcs((const float4*)(cp + e + STRIDE));
            float4 v2 = __ldcs((const float4*)(cp + e + 2 * STRIDE));
            float4 v3 = __ldcs((const float4*)(cp + e + 3 * STRIDE));
            float4 v4 = __ldcs((const float4*)(cp + e + 4 * STRIDE));
            // rolling prefetch: stay 2 bursts ahead (bursts 2,3 during iters 0,1)
            if (i < 2 && tid < 160)
                asm volatile("prefetch.global.L2 [%0];"
                             :: "l"(cp + (i + 2) * 5120 + tid * 32));
            acc0 = fmaf(s_w[(e)                / CN], term4s(v0), acc0);
            acc1 = fmaf(s_w[(e + STRIDE)       / CN], term4s(v1), acc1);
            acc0 = fmaf(s_w[(e + 2 * STRIDE)   / CN], term4s(v2), acc0);
            acc1 = fmaf(s_w[(e + 3 * STRIDE)   / CN], term4s(v3), acc1);
            acc0 = fmaf(s_w[(e + 4 * STRIDE)   / CN], term4s(v4), acc0);
            e += 5 * STRIDE;
        }
    } else {
        const int nE = nA * CN;
        int e = tid * 4;
        #pragma unroll 1
        for (; e + 3 * STRIDE < nE; e += 4 * STRIDE) {
            float4 v0 = __ldcs((const float4*)(cp + e));
            float4 v1 = __ldcs((const float4*)(cp + e + STRIDE));
            float4 v2 = __ldcs((const float4*)(cp + e + 2 * STRIDE));
            float4 v3 = __ldcs((const float4*)(cp + e + 3 * STRIDE));
            acc0 = fmaf(s_w[(e)              / CN], term4s(v0), acc0);
            acc1 = fmaf(s_w[(e + STRIDE)     / CN], term4s(v1), acc1);
            acc0 = fmaf(s_w[(e + 2 * STRIDE) / CN], term4s(v2), acc0);
            acc1 = fmaf(s_w[(e + 3 * STRIDE) / CN], term4s(v3), acc1);
        }
        #pragma unroll 1
        for (; e < nE; e += STRIDE) {
            float4 v = __ldcs((const float4*)(cp + e));
            acc0 = fmaf(s_w[e / CN], term4s(v), acc0);
        }
    }
    l_cls += acc0 + acc1;

    // ---- block reduce ----
    const unsigned fullm = 0xffffffffu;
    for (int o = 16; o > 0; o >>= 1) {
        l_cls += __shfl_down_sync(fullm, l_cls, o);
        l_reg += __shfl_down_sync(fullm, l_reg, o);
        l_np  += __shfl_down_sync(fullm, l_np,  o);
    }
    int wid = tid >> 5, lane = tid & 31;
    if (lane == 0) { s_rc[wid] = l_cls; s_rr[wid] = l_reg; s_rn[wid] = l_np; }
    __syncthreads();

    if (tid == 0) {
        float tc = 0.0f, tr = 0.0f; int tn = 0;
        #pragma unroll
        for (int w = 0; w < BLK / 32; w++) { tc += s_rc[w]; tr += s_rr[w]; tn += s_rn[w]; }
        atomicAdd(&g_cls[b], (double)tc);
        atomicAdd(&g_reg[b], (double)tr);
        atomicAdd(&g_np[b], tn);
        __threadfence();
        unsigned prev = atomicAdd(&g_done, 1u);
        s_last = (prev == NBLOCKS - 1);
    }
    __syncthreads();

    // ---- last block finalizes and resets accumulators for the next replay ----
    if (s_last && tid == 0) {
        float cs = 0.0f, rs = 0.0f;
        #pragma unroll
        for (int bb = 0; bb < BN; bb++) {
            float np = (float)g_np[bb];
            float c = (float)g_cls[bb] / fmaxf(np, 1.0f);
            float r = (np > 0.0f) ? (float)g_reg[bb] / fmaxf(np * 4.0f, 1.0f) : 0.0f;
            cs += c; rs += r;
            g_cls[bb] = 0.0; g_reg[bb] = 0.0; g_np[bb] = 0;
        }
        out[0] = cs * 0.125f;
        out[1] = rs * 0.125f;
        __threadfence();
        g_done = 0u;
    }
}

extern "C" void kernel_launch(void* const* d_in, const int* in_sizes, int n_in,
                              void* d_out, int out_size) {
    const float *cls = nullptr, *reg = nullptr, *anc = nullptr, *lab = nullptr;
    for (int i = 0; i < n_in; i++) {
        switch (in_sizes[i]) {
            case 76800000: cls = (const float*)d_in[i]; break;  // [8,120000,80]
            case 3840000:  reg = (const float*)d_in[i]; break;  // [8,120000,4]
            case 480000:   anc = (const float*)d_in[i]; break;  // [1,120000,4]
            case 1280:     lab = (const float*)d_in[i]; break;  // [8,32,5]
        }
    }
    dim3 grid(GX, BN);
    focal_main<<<grid, BLK>>>(cls, reg, anc, lab, (float*)d_out);
}

// round 17
// speedup vs baseline: 1.0615x; 1.0615x over previous
#include <cuda_runtime.h>
#include <math.h>

#define AN 120000
#define BN 8
#define CN 80
#define MN 32
#define NVALID 24
#define BLK 256
#define GX ((AN + BLK - 1) / BLK)     // 469
#define NBLOCKS (GX * BN)             // 3752
#define LN2 0.69314718055994530942f

__device__ double g_cls[BN];
__device__ double g_reg[BN];
__device__ int    g_np[BN];
__device__ unsigned int g_done;

__device__ __forceinline__ float smooth_l1(float d) {
    float ad = fabsf(d);
    return (ad <= (1.0f / 9.0f)) ? 4.5f * ad * ad : (ad - 0.5f / 9.0f);
}

// one group's focal sum in log2 domain
__device__ __forceinline__ float term4s(float4 v) {
    float o0 = fmaxf(1.0f - v.x, 1e-4f);
    float o1 = fmaxf(1.0f - v.y, 1e-4f);
    float o2 = fmaxf(1.0f - v.z, 1e-4f);
    float o3 = fmaxf(1.0f - v.w, 1e-4f);
    float s = v.x * v.x * __log2f(o0);
    s = fmaf(v.y * v.y, __log2f(o1), s);
    s = fmaf(v.z * v.z, __log2f(o2), s);
    s = fmaf(v.w * v.w, __log2f(o3), s);
    return s;
}

__global__ __launch_bounds__(BLK, 8) void focal_main(
    const float* __restrict__ cls,
    const float* __restrict__ reg,
    const float* __restrict__ anc,
    const float* __restrict__ lab,
    float* __restrict__ out)
{
    __shared__ float4  s_xy[MN];     // x1,y1,x2,y2 per gt box
    __shared__ float   s_area[MN];   // box area
    __shared__ float   s_cls[MN];    // box class
    __shared__ unsigned s_msk;       // validity ballot
    __shared__ float   s_w[BLK];     // per-anchor weight: 0 (ignore) or -0.75*ln2
    __shared__ float   s_rc[BLK / 32];
    __shared__ float   s_rr[BLK / 32];
    __shared__ int     s_rn[BLK / 32];
    __shared__ bool    s_last;

    const int b   = blockIdx.y;
    const int a0  = blockIdx.x * BLK;
    const int tid = threadIdx.x;
    const int nA  = min(BLK, AN - a0);

    // ---- entry prefetch only (phase-A shadow): bursts 0+1, one line/thread ----
    // 320 lines = 40KB. tid<256 covers burst 0 + half of burst 1; tid<64 adds rest.
    const float* cp = cls + ((size_t)b * AN + (size_t)a0) * CN;
    {
        const int nF = nA * CN;
        if (tid * 32 < nF)
            asm volatile("prefetch.global.L2 [%0];" :: "l"(cp + tid * 32));
        if (tid < 64 && (tid + 256) * 32 < nF)
            asm volatile("prefetch.global.L2 [%0];" :: "l"(cp + (tid + 256) * 32));
    }

    if (tid < 32) {
        const float* L = lab + ((size_t)b * MN + tid) * 5;
        float x1 = L[0], y1 = L[1], x2 = L[2], y2 = L[3], cl = L[4];
        s_xy[tid]   = make_float4(x1, y1, x2, y2);
        s_area[tid] = __fmul_rn(x2 - x1, y2 - y1);
        s_cls[tid]  = cl;
        unsigned m = __ballot_sync(0xffffffffu, cl != -1.0f);
        if (tid == 0) s_msk = m;
    }
    __syncthreads();

    float l_cls = 0.0f;
    float l_reg = 0.0f;
    int   l_np  = 0;
    float w_log2 = 0.0f;

    // ---- phase A: per-anchor IoU argmax, regression loss, positive correction ----
    if (tid < nA) {
        const int a = a0 + tid;
        const float4 av = __ldg(((const float4*)anc) + a);
        const float ax1 = av.x, ay1 = av.y, ax2 = av.z, ay2 = av.w;
        const float aw = ax2 - ax1, ah = ay2 - ay1;
        const float area_a = __fmul_rn(aw, ah);

        // argmax via cross-multiply: iou monotone in inter/sab
        float b_inter = -1.0f, b_sab = 1.0f;
        int   b_m = 0;

        if (s_msk == 0x00FFFFFFu) {
            // fast path: boxes 0..23 valid, 24..31 invalid (dataset invariant)
            #pragma unroll
            for (int m = 0; m < NVALID; m++) {
                float4 bx = s_xy[m];
                float iw = fmaxf(fminf(ax2, bx.z) - fmaxf(ax1, bx.x), 0.0f);
                float ih = fmaxf(fminf(ay2, bx.w) - fmaxf(ay1, bx.y), 0.0f);
                float inter = iw * ih;
                float sab   = area_a + s_area[m];
                if (inter * b_sab > b_inter * sab) {
                    b_inter = inter; b_sab = sab; b_m = m;
                }
            }
        } else {
            // generic fallback (any validity pattern)
            #pragma unroll
            for (int m = 0; m < MN; m++) {
                if (s_cls[m] < 0.0f) continue;
                float4 bx = s_xy[m];
                float iw = fmaxf(fminf(ax2, bx.z) - fmaxf(ax1, bx.x), 0.0f);
                float ih = fmaxf(fminf(ay2, bx.w) - fmaxf(ay1, bx.y), 0.0f);
                float inter = iw * ih;
                float sab   = area_a + s_area[m];
                if (inter * b_sab > b_inter * sab) {
                    b_inter = inter; b_sab = sab; b_m = m;
                }
            }
        }

        // exact IEEE recompute of winner's IoU (matches reference op-for-op)
        float4 bx = s_xy[b_m];
        float ab  = s_area[b_m];
        float iw = fmaxf(__fadd_rn(fminf(ax2, bx.z), -fmaxf(ax1, bx.x)), 0.0f);
        float ih = fmaxf(__fadd_rn(fminf(ay2, bx.w), -fmaxf(ay1, bx.y)), 0.0f);
        float inter = __fmul_rn(iw, ih);
        float ua = fmaxf(__fadd_rn(__fadd_rn(area_a, ab), -inter), 1e-8f);
        float iou = __fdiv_rn(inter, ua);

        if (iou >= 0.5f) {                       // positive anchor
            int code = (int)s_cls[b_m];
            l_np = 1;
            w_log2 = -0.75f * LN2;
            float gw_raw = bx.z - bx.x;
            float gh_raw = bx.w - bx.y;
            float gcx = bx.x + 0.5f * gw_raw;
            float gcy = bx.y + 0.5f * gh_raw;
            float gw = fmaxf(gw_raw, 1.0f);
            float gh = fmaxf(gh_raw, 1.0f);
            float acx = ax1 + 0.5f * aw;
            float acy = ay1 + 0.5f * ah;
            float t0 = __fdiv_rn(__fdiv_rn(gcx - acx, aw), 0.1f);
            float t1 = __fdiv_rn(__fdiv_rn(gcy - acy, ah), 0.1f);
            float t2 = __fdiv_rn(__logf(__fdiv_rn(gw, aw)), 0.2f);
            float t3 = __fdiv_rn(__logf(__fdiv_rn(gh, ah)), 0.2f);
            float4 rv = __ldg(((const float4*)reg) + ((size_t)b * AN + a));
            l_reg = smooth_l1(t0 - rv.x) + smooth_l1(t1 - rv.y)
                  + smooth_l1(t2 - rv.z) + smooth_l1(t3 - rv.w);
            // target-class correction: cancel streamed non-target term, add positive term
            float p    = __ldg(cls + ((size_t)b * AN + a) * CN + code);
            float pc   = fminf(fmaxf(p, 1e-4f), 1.0f - 1e-4f);
            float ompc = 1.0f - pc;
            float omp  = fmaxf(1.0f - p, 1e-4f);
            l_cls = 0.25f * ompc * ompc * (-__logf(pc))
                  + 0.75f * LN2 * (p * p * __log2f(omp));
        } else if (iou < 0.4f) {
            w_log2 = -0.75f * LN2;               // negative anchor
        }                                        // else ignore: w stays 0
    }
    s_w[tid] = w_log2;
    __syncthreads();   // load-bearing: synchronizes warps' LDG wavefronts

    // ---- phase B: block-strided weighted stream, MLP=5 (no in-loop prefetch) ----
    float acc0 = 0.0f, acc1 = 0.0f;
    const int STRIDE = BLK * 4;           // 1024 floats

    if (nA == BLK) {
        int e = tid * 4;
        #pragma unroll 1
        for (int i = 0; i < 4; i++) {
            float4 v0 = __ldcs((const float4*)(cp + e));
            float4 v1 = __ldcs((const float4*)(cp + e + STRIDE));
            float4 v2 = __ldcs((const float4*)(cp + e + 2 * STRIDE));
            float4 v3 = __ldcs((const float4*)(cp + e + 3 * STRIDE));
            float4 v4 = __ldcs((const float4*)(cp + e + 4 * STRIDE));
            acc0 = fmaf(s_w[(e)                / CN], term4s(v0), acc0);
            acc1 = fmaf(s_w[(e + STRIDE)       / CN], term4s(v1), acc1);
            acc0 = fmaf(s_w[(e + 2 * STRIDE)   / CN], term4s(v2), acc0);
            acc1 = fmaf(s_w[(e + 3 * STRIDE)   / CN], term4s(v3), acc1);
            acc0 = fmaf(s_w[(e + 4 * STRIDE)   / CN], term4s(v4), acc0);
            e += 5 * STRIDE;
        }
    } else {
        const int nE = nA * CN;
        int e = tid * 4;
        #pragma unroll 1
        for (; e + 3 * STRIDE < nE; e += 4 * STRIDE) {
            float4 v0 = __ldcs((const float4*)(cp + e));
            float4 v1 = __ldcs((const float4*)(cp + e + STRIDE));
            float4 v2 = __ldcs((const float4*)(cp + e + 2 * STRIDE));
            float4 v3 = __ldcs((const float4*)(cp + e + 3 * STRIDE));
            acc0 = fmaf(s_w[(e)              / CN], term4s(v0), acc0);
            acc1 = fmaf(s_w[(e + STRIDE)     / CN], term4s(v1), acc1);
            acc0 = fmaf(s_w[(e + 2 * STRIDE) / CN], term4s(v2), acc0);
            acc1 = fmaf(s_w[(e + 3 * STRIDE) / CN], term4s(v3), acc1);
        }
        #pragma unroll 1
        for (; e < nE; e += STRIDE) {
            float4 v = __ldcs((const float4*)(cp + e));
            acc0 = fmaf(s_w[e / CN], term4s(v), acc0);
        }
    }
    l_cls += acc0 + acc1;

    // ---- block reduce ----
    const unsigned fullm = 0xffffffffu;
    for (int o = 16; o > 0; o >>= 1) {
        l_cls += __shfl_down_sync(fullm, l_cls, o);
        l_reg += __shfl_down_sync(fullm, l_reg, o);
        l_np  += __shfl_down_sync(fullm, l_np,  o);
    }
    int wid = tid >> 5, lane = tid & 31;
    if (lane == 0) { s_rc[wid] = l_cls; s_rr[wid] = l_reg; s_rn[wid] = l_np; }
    __syncthreads();

    if (tid == 0) {
        float tc = 0.0f, tr = 0.0f; int tn = 0;
        #pragma unroll
        for (int w = 0; w < BLK / 32; w++) { tc += s_rc[w]; tr += s_rr[w]; tn += s_rn[w]; }
        atomicAdd(&g_cls[b], (double)tc);
        atomicAdd(&g_reg[b], (double)tr);
        atomicAdd(&g_np[b], tn);
        __threadfence();
        unsigned prev = atomicAdd(&g_done, 1u);
        s_last = (prev == NBLOCKS - 1);
    }
    __syncthreads();

    // ---- last block finalizes and resets accumulators for the next replay ----
    if (s_last && tid == 0) {
        float cs = 0.0f, rs = 0.0f;
        #pragma unroll
        for (int bb = 0; bb < BN; bb++) {
            float np = (float)g_np[bb];
            float c = (float)g_cls[bb] / fmaxf(np, 1.0f);
            float r = (np > 0.0f) ? (float)g_reg[bb] / fmaxf(np * 4.0f, 1.0f) : 0.0f;
            cs += c; rs += r;
            g_cls[bb] = 0.0; g_reg[bb] = 0.0; g_np[bb] = 0;
        }
        out[0] = cs * 0.125f;
        out[1] = rs * 0.125f;
        __threadfence();
        g_done = 0u;
    }
}

extern "C" void kernel_launch(void* const* d_in, const int* in_sizes, int n_in,
                              void* d_out, int out_size) {
    const float *cls = nullptr, *reg = nullptr, *anc = nullptr, *lab = nullptr;
    for (int i = 0; i < n_in; i++) {
        switch (in_sizes[i]) {
            case 76800000: cls = (const float*)d_in[i]; break;  // [8,120000,80]
            case 3840000:  reg = (const float*)d_in[i]; break;  // [8,120000,4]
            case 480000:   anc = (const float*)d_in[i]; break;  // [1,120000,4]
            case 1280:     lab = (const float*)d_in[i]; break;  // [8,32,5]
        }
    }
    dim3 grid(GX, BN);
    focal_main<<<grid, BLK>>>(cls, reg, anc, lab, (float*)d_out);
}